// round 2
// baseline (speedup 1.0000x reference)
#include <cuda_runtime.h>

// Problem constants
// B=16, L=1024, H=8, E=64, WIN=1024, G=64, D_SEL=1
#define NB 16
#define NL 1024
#define NH 8
#define NE 64
#define NG 64

// Scratch (device globals: allocation-free rule)
__device__ float g_m[NB * NH * NL];        // [b][h][n]  tanh-MLP, reshaped order
__device__ float g_T[NB * NH * NE * NG];   // [b][h][e][g]

// ---------- packed f32x2 helpers ----------
__device__ __forceinline__ unsigned long long pack2(float a, float b) {
    unsigned long long r;
    asm("mov.b64 %0, {%1, %2};" : "=l"(r) : "f"(a), "f"(b));
    return r;
}
__device__ __forceinline__ void fma2(unsigned long long& d, unsigned long long a, unsigned long long b) {
    asm("fma.rn.f32x2 %0, %1, %2, %0;" : "+l"(d) : "l"(a), "l"(b));
}
__device__ __forceinline__ float2 unpack2(unsigned long long v) {
    float2 r;
    r.x = __uint_as_float((unsigned int)(v & 0xffffffffull));
    r.y = __uint_as_float((unsigned int)(v >> 32));
    return r;
}

// ---------- kernel 0: zero output + g_T ----------
__global__ void k0_zero(float* __restrict__ out) {
    int i = blockIdx.x * 256 + threadIdx.x;   // grid covers exactly 524288
    out[i] = 0.0f;
    g_T[i] = 0.0f;
}

// ---------- kernel 1: MLP  m[b,h,n] = tanh(x @ W^T + b) with raw-reshape mapping ----------
// tanh_out[r, c] -> m[b = r>>10, h = (r&1023)>>7, n = ((r&1023)&127)*8 + c]
__global__ void __launch_bounds__(256) k1_mlp(const float* __restrict__ x,
                                              const float* __restrict__ w,
                                              const float* __restrict__ bias) {
    __shared__ __align__(16) float sw[8 * 1024];
    __shared__ float sb[8];
    int tid = threadIdx.x;
    for (int i = tid; i < 8192; i += 256) sw[i] = w[i];
    if (tid < 8) sb[tid] = bias[tid];
    __syncthreads();

    int warp = tid >> 5, lane = tid & 31;
#pragma unroll
    for (int rr = 0; rr < 2; ++rr) {
        int row = blockIdx.x * 16 + warp * 2 + rr;
        const float4* xr = (const float4*)(x + (long)row * 1024);
        float acc[8];
#pragma unroll
        for (int h = 0; h < 8; ++h) acc[h] = 0.0f;
#pragma unroll
        for (int j = 0; j < 8; ++j) {
            int k4 = lane * 4 + j * 128;
            float4 xv = xr[k4 >> 2];
#pragma unroll
            for (int h = 0; h < 8; ++h) {
                float4 wv = *(const float4*)&sw[h * 1024 + k4];
                acc[h] += xv.x * wv.x + xv.y * wv.y + xv.z * wv.z + xv.w * wv.w;
            }
        }
#pragma unroll
        for (int h = 0; h < 8; ++h) {
#pragma unroll
            for (int off = 16; off > 0; off >>= 1)
                acc[h] += __shfl_xor_sync(0xffffffffu, acc[h], off);
        }
        if (lane < 8) {
            float v = tanhf(acc[lane] + sb[lane]);
            int b = row >> 10;
            int j = row & 1023;
            int h = j >> 7;
            int n = ((j & 127) << 3) + lane;
            g_m[(b * 8 + h) * 1024 + n] = v;
        }
    }
}

// ---------- kernel 2: T[b,h,e,g] = sum_n Q[b,n,h,e] * relu(m[b,h,n] * selW[h,g]) ----------
// grid (chunk=8, H, B), 256 threads; each CTA covers 128 n, atomic-accumulates into g_T.
__global__ void __launch_bounds__(256) k2_T(const float* __restrict__ q,
                                            const float* __restrict__ selW) {
    int chunk = blockIdx.x, h = blockIdx.y, b = blockIdx.z;
    __shared__ __align__(16) float sQ[16][64];
    __shared__ __align__(16) float sS[16][64];
    __shared__ __align__(16) float sW[64];
    int tid = threadIdx.x;
    if (tid < 64) sW[tid] = selW[h * 64 + tid];

    int te = tid & 15, tg = tid >> 4;
    int e0 = te * 4, g0 = tg * 4;
    unsigned long long acc[4][2];
#pragma unroll
    for (int i = 0; i < 4; ++i) { acc[i][0] = 0ull; acc[i][1] = 0ull; }

    const float* mptr = g_m + (b * 8 + h) * 1024 + chunk * 128;
    int ni = tid >> 4, c4 = (tid & 15) * 4;   // staging roles
    __syncthreads();

    for (int t = 0; t < 8; ++t) {
        int nb = chunk * 128 + t * 16;
        float4 qv = *(const float4*)(q + (((long)(b * 1024 + nb + ni) * 8 + h) * 64 + c4));
        float mv = mptr[t * 16 + ni];
        float4 w4 = *(const float4*)&sW[c4];
        float4 sv;
        sv.x = fmaxf(mv * w4.x, 0.0f);
        sv.y = fmaxf(mv * w4.y, 0.0f);
        sv.z = fmaxf(mv * w4.z, 0.0f);
        sv.w = fmaxf(mv * w4.w, 0.0f);
        *(float4*)&sQ[ni][c4] = qv;
        *(float4*)&sS[ni][c4] = sv;
        __syncthreads();
#pragma unroll
        for (int i = 0; i < 16; ++i) {
            float4 qq = *(const float4*)&sQ[i][e0];
            ulonglong2 ss = *(const ulonglong2*)&sS[i][g0];
            unsigned long long q2;
            q2 = pack2(qq.x, qq.x); fma2(acc[0][0], q2, ss.x); fma2(acc[0][1], q2, ss.y);
            q2 = pack2(qq.y, qq.y); fma2(acc[1][0], q2, ss.x); fma2(acc[1][1], q2, ss.y);
            q2 = pack2(qq.z, qq.z); fma2(acc[2][0], q2, ss.x); fma2(acc[2][1], q2, ss.y);
            q2 = pack2(qq.w, qq.w); fma2(acc[3][0], q2, ss.x); fma2(acc[3][1], q2, ss.y);
        }
        __syncthreads();
    }

    long base = ((long)((b * 8 + h) * 64 + e0)) * 64 + g0;
#pragma unroll
    for (int i = 0; i < 4; ++i) {
#pragma unroll
        for (int jp = 0; jp < 2; ++jp) {
            float2 v = unpack2(acc[i][jp]);
            atomicAdd(&g_T[base + i * 64 + jp * 2 + 0], v.x);
            atomicAdd(&g_T[base + i * 64 + jp * 2 + 1], v.y);
        }
    }
}

// ---------- kernel 3: logits = K·T, softmax over g, V += values^T · P ----------
// grid (ns=8, H, B), 256 threads; each CTA covers 128 s in 4 subtiles of 32.
__global__ void __launch_bounds__(256) k3_attn(const float* __restrict__ K,
                                               const float* __restrict__ V,
                                               float* __restrict__ out) {
    int ns = blockIdx.x, h = blockIdx.y, b = blockIdx.z;
    __shared__ __align__(16) float sT[64][64];    // [e][g]
    __shared__ __align__(16) float sKt[64][34];   // [e][s], padded
    __shared__ __align__(16) float sV[32][64];    // [s][e]
    __shared__ __align__(16) float sP[32][64];    // [s][g]
    int tid = threadIdx.x;

    // Load T tile once
    const float4* Tp = (const float4*)(g_T + (long)((b * 8 + h)) * 4096);
    float4* sTp = (float4*)&sT[0][0];
#pragma unroll
    for (int i = 0; i < 4; ++i) sTp[i * 256 + tid] = Tp[i * 256 + tid];

    // phase A map: 2 s-rows x 4 g per thread; row group = 16 lanes (half warp)
    int ts = tid >> 4;        // ss = ts*2
    int tgA = tid & 15;       // gA = tgA*4
    // phase B map: 4 e x 4 g per thread
    int te = tid & 15;        // e0 = te*4
    int tgB = tid >> 4;       // gB = tgB*4

    unsigned long long accV[4][2];
#pragma unroll
    for (int i = 0; i < 4; ++i) { accV[i][0] = 0ull; accV[i][1] = 0ull; }

    for (int st = 0; st < 4; ++st) {
        int s0 = ns * 128 + st * 32;
        __syncthreads();
        // stage K (transposed) and values (straight)
#pragma unroll
        for (int v = 0; v < 2; ++v) {
            int idx = v * 256 + tid;
            int si = idx >> 4, e4 = (idx & 15) * 4;
            long gbase = ((long)(b * 1024 + s0 + si) * 8 + h) * 64 + e4;
            float4 kv = *(const float4*)(K + gbase);
            sKt[e4 + 0][si] = kv.x;
            sKt[e4 + 1][si] = kv.y;
            sKt[e4 + 2][si] = kv.z;
            sKt[e4 + 3][si] = kv.w;
            *(float4*)&sV[si][e4] = *(const float4*)(V + gbase);
        }
        __syncthreads();

        // phase A: logits[2 s][4 g]
        unsigned long long accL[2][2];
        accL[0][0] = accL[0][1] = accL[1][0] = accL[1][1] = 0ull;
#pragma unroll 16
        for (int e = 0; e < 64; ++e) {
            float2 kk = *(const float2*)&sKt[e][ts * 2];
            ulonglong2 tt = *(const ulonglong2*)&sT[e][tgA * 4];
            unsigned long long k0 = pack2(kk.x, kk.x);
            unsigned long long k1 = pack2(kk.y, kk.y);
            fma2(accL[0][0], k0, tt.x); fma2(accL[0][1], k0, tt.y);
            fma2(accL[1][0], k1, tt.x); fma2(accL[1][1], k1, tt.y);
        }
        // softmax over 64 g (4 local + 16 lanes), scale = 1/sqrt(64)
#pragma unroll
        for (int r = 0; r < 2; ++r) {
            float2 a = unpack2(accL[r][0]);
            float2 c = unpack2(accL[r][1]);
            float l0 = 0.125f * a.x, l1 = 0.125f * a.y, l2 = 0.125f * c.x, l3 = 0.125f * c.y;
            float mx = fmaxf(fmaxf(l0, l1), fmaxf(l2, l3));
#pragma unroll
            for (int off = 8; off > 0; off >>= 1)
                mx = fmaxf(mx, __shfl_xor_sync(0xffffffffu, mx, off));
            float p0 = __expf(l0 - mx), p1 = __expf(l1 - mx);
            float p2 = __expf(l2 - mx), p3 = __expf(l3 - mx);
            float sum = p0 + p1 + p2 + p3;
#pragma unroll
            for (int off = 8; off > 0; off >>= 1)
                sum += __shfl_xor_sync(0xffffffffu, sum, off);
            float inv = 1.0f / sum;
            *(float4*)&sP[ts * 2 + r][tgA * 4] = make_float4(p0 * inv, p1 * inv, p2 * inv, p3 * inv);
        }
        __syncthreads();

        // phase B: accV[e][g] += v[s][e] * P[s][g]
#pragma unroll 8
        for (int s = 0; s < 32; ++s) {
            float4 vv = *(const float4*)&sV[s][te * 4];
            ulonglong2 pp = *(const ulonglong2*)&sP[s][tgB * 4];
            unsigned long long v2;
            v2 = pack2(vv.x, vv.x); fma2(accV[0][0], v2, pp.x); fma2(accV[0][1], v2, pp.y);
            v2 = pack2(vv.y, vv.y); fma2(accV[1][0], v2, pp.x); fma2(accV[1][1], v2, pp.y);
            v2 = pack2(vv.z, vv.z); fma2(accV[2][0], v2, pp.x); fma2(accV[2][1], v2, pp.y);
            v2 = pack2(vv.w, vv.w); fma2(accV[3][0], v2, pp.x); fma2(accV[3][1], v2, pp.y);
        }
    }

    // epilogue: out[b, e, h, g] layout [16,64,8,64]
#pragma unroll
    for (int i = 0; i < 4; ++i) {
        int e = te * 4 + i;
        long obase = ((long)(b * 64 + e) * 8 + h) * 64 + tgB * 4;
#pragma unroll
        for (int jp = 0; jp < 2; ++jp) {
            float2 v = unpack2(accV[i][jp]);
            atomicAdd(&out[obase + jp * 2 + 0], v.x);
            atomicAdd(&out[obase + jp * 2 + 1], v.y);
        }
    }
}

extern "C" void kernel_launch(void* const* d_in, const int* in_sizes, int n_in,
                              void* d_out, int out_size) {
    const float* q  = (const float*)d_in[0];
    const float* k  = (const float*)d_in[1];
    const float* v  = (const float*)d_in[2];
    const float* x  = (const float*)d_in[3];
    const float* mw = (const float*)d_in[4];
    const float* mb = (const float*)d_in[5];
    const float* sW = (const float*)d_in[6];
    (void)in_sizes; (void)n_in; (void)out_size;
    float* out = (float*)d_out;

    k0_zero<<<2048, 256>>>(out);                 // zero out + g_T (524288 each)
    k1_mlp<<<1024, 256>>>(x, mw, mb);            // 16 rows per CTA
    k2_T<<<dim3(8, NH, NB), 256>>>(q, sW);       // T = Q^T * sel
    k3_attn<<<dim3(8, NH, NB), 256>>>(k, v, out);// logits/softmax/V
}

// round 3
// speedup vs baseline: 1.0410x; 1.0410x over previous
#include <cuda_runtime.h>

// Problem constants
// B=16, L=1024, H=8, E=64, WIN=1024, G=64, D_SEL=1
#define NB 16
#define NL 1024
#define NH 8
#define NE 64
#define NG 64

// Scratch (device globals: allocation-free rule)
__device__ float g_m[NB * NH * NL];        // [b][h][n]  tanh-MLP, reshaped order
__device__ float g_T[NB * NH * NE * NG];   // [b][h][e][g]

// ---------- packed f32x2 helpers ----------
__device__ __forceinline__ unsigned long long pack2(float a, float b) {
    unsigned long long r;
    asm("mov.b64 %0, {%1, %2};" : "=l"(r) : "f"(a), "f"(b));
    return r;
}
__device__ __forceinline__ void fma2(unsigned long long& d, unsigned long long a, unsigned long long b) {
    asm("fma.rn.f32x2 %0, %1, %2, %0;" : "+l"(d) : "l"(a), "l"(b));
}
__device__ __forceinline__ float2 unpack2(unsigned long long v) {
    float2 r;
    r.x = __uint_as_float((unsigned int)(v & 0xffffffffull));
    r.y = __uint_as_float((unsigned int)(v >> 32));
    return r;
}

// ---------- kernel 0: zero output + g_T ----------
__global__ void k0_zero(float* __restrict__ out) {
    int i = blockIdx.x * 256 + threadIdx.x;   // grid covers exactly 524288
    out[i] = 0.0f;
    g_T[i] = 0.0f;
}

// ---------- kernel 1: MLP  m[b,h,n] = tanh(x @ W^T + b) with raw-reshape mapping ----------
// tanh_out[r, c] -> m[b = r>>10, h = (r&1023)>>7, n = ((r&1023)&127)*8 + c]
__global__ void __launch_bounds__(256) k1_mlp(const float* __restrict__ x,
                                              const float* __restrict__ w,
                                              const float* __restrict__ bias) {
    __shared__ __align__(16) float sw[8 * 1024];
    __shared__ float sb[8];
    int tid = threadIdx.x;
    for (int i = tid; i < 8192; i += 256) sw[i] = w[i];
    if (tid < 8) sb[tid] = bias[tid];
    __syncthreads();

    int warp = tid >> 5, lane = tid & 31;
#pragma unroll
    for (int rr = 0; rr < 2; ++rr) {
        int row = blockIdx.x * 16 + warp * 2 + rr;
        const float4* xr = (const float4*)(x + (long)row * 1024);
        float acc[8];
#pragma unroll
        for (int h = 0; h < 8; ++h) acc[h] = 0.0f;
#pragma unroll
        for (int j = 0; j < 8; ++j) {
            int k4 = lane * 4 + j * 128;
            float4 xv = xr[k4 >> 2];
#pragma unroll
            for (int h = 0; h < 8; ++h) {
                float4 wv = *(const float4*)&sw[h * 1024 + k4];
                acc[h] += xv.x * wv.x + xv.y * wv.y + xv.z * wv.z + xv.w * wv.w;
            }
        }
#pragma unroll
        for (int h = 0; h < 8; ++h) {
#pragma unroll
            for (int off = 16; off > 0; off >>= 1)
                acc[h] += __shfl_xor_sync(0xffffffffu, acc[h], off);
        }
        if (lane < 8) {
            float v = tanhf(acc[lane] + sb[lane]);
            int b = row >> 10;
            int j = row & 1023;
            int h = j >> 7;
            int n = ((j & 127) << 3) + lane;
            g_m[(b * 8 + h) * 1024 + n] = v;
        }
    }
}

// ---------- kernel 2: T[b,h,e,g] = sum_n Q[b,n,h,e] * relu(m[b,h,n] * selW[h,g]) ----------
// grid (chunk=8, H, B), 256 threads; each CTA covers 128 n, atomic-accumulates into g_T.
__global__ void __launch_bounds__(256) k2_T(const float* __restrict__ q,
                                            const float* __restrict__ selW) {
    int chunk = blockIdx.x, h = blockIdx.y, b = blockIdx.z;
    __shared__ __align__(16) float sQ[16][64];
    __shared__ __align__(16) float sS[16][64];
    __shared__ __align__(16) float sW[64];
    int tid = threadIdx.x;
    if (tid < 64) sW[tid] = selW[h * 64 + tid];

    int te = tid & 15, tg = tid >> 4;
    int e0 = te * 4, g0 = tg * 4;
    unsigned long long acc[4][2];
#pragma unroll
    for (int i = 0; i < 4; ++i) { acc[i][0] = 0ull; acc[i][1] = 0ull; }

    const float* mptr = g_m + (b * 8 + h) * 1024 + chunk * 128;
    int ni = tid >> 4, c4 = (tid & 15) * 4;   // staging roles
    __syncthreads();

    for (int t = 0; t < 8; ++t) {
        int nb = chunk * 128 + t * 16;
        float4 qv = *(const float4*)(q + (((long)(b * 1024 + nb + ni) * 8 + h) * 64 + c4));
        float mv = mptr[t * 16 + ni];
        float4 w4 = *(const float4*)&sW[c4];
        float4 sv;
        sv.x = fmaxf(mv * w4.x, 0.0f);
        sv.y = fmaxf(mv * w4.y, 0.0f);
        sv.z = fmaxf(mv * w4.z, 0.0f);
        sv.w = fmaxf(mv * w4.w, 0.0f);
        *(float4*)&sQ[ni][c4] = qv;
        *(float4*)&sS[ni][c4] = sv;
        __syncthreads();
#pragma unroll
        for (int i = 0; i < 16; ++i) {
            float4 qq = *(const float4*)&sQ[i][e0];
            ulonglong2 ss = *(const ulonglong2*)&sS[i][g0];
            unsigned long long q2;
            q2 = pack2(qq.x, qq.x); fma2(acc[0][0], q2, ss.x); fma2(acc[0][1], q2, ss.y);
            q2 = pack2(qq.y, qq.y); fma2(acc[1][0], q2, ss.x); fma2(acc[1][1], q2, ss.y);
            q2 = pack2(qq.z, qq.z); fma2(acc[2][0], q2, ss.x); fma2(acc[2][1], q2, ss.y);
            q2 = pack2(qq.w, qq.w); fma2(acc[3][0], q2, ss.x); fma2(acc[3][1], q2, ss.y);
        }
        __syncthreads();
    }

    long base = ((long)((b * 8 + h) * 64 + e0)) * 64 + g0;
#pragma unroll
    for (int i = 0; i < 4; ++i) {
#pragma unroll
        for (int jp = 0; jp < 2; ++jp) {
            float2 v = unpack2(acc[i][jp]);
            atomicAdd(&g_T[base + i * 64 + jp * 2 + 0], v.x);
            atomicAdd(&g_T[base + i * 64 + jp * 2 + 1], v.y);
        }
    }
}

// ---------- kernel 3: logits = K·T, softmax over g, V += values^T · P ----------
// grid (ns=8, H, B), 256 threads; each CTA covers 128 s in 4 subtiles of 32.
__global__ void __launch_bounds__(256) k3_attn(const float* __restrict__ K,
                                               const float* __restrict__ V,
                                               float* __restrict__ out) {
    int ns = blockIdx.x, h = blockIdx.y, b = blockIdx.z;
    __shared__ __align__(16) float sT[64][64];    // [e][g]
    __shared__ __align__(16) float sKt[64][34];   // [e][s], padded
    __shared__ __align__(16) float sV[32][64];    // [s][e]
    __shared__ __align__(16) float sP[32][64];    // [s][g]
    int tid = threadIdx.x;

    // Load T tile once
    const float4* Tp = (const float4*)(g_T + (long)((b * 8 + h)) * 4096);
    float4* sTp = (float4*)&sT[0][0];
#pragma unroll
    for (int i = 0; i < 4; ++i) sTp[i * 256 + tid] = Tp[i * 256 + tid];

    // phase A map: 2 s-rows x 4 g per thread; row group = 16 lanes (half warp)
    int ts = tid >> 4;        // ss = ts*2
    int tgA = tid & 15;       // gA = tgA*4
    // phase B map: 4 e x 4 g per thread
    int te = tid & 15;        // e0 = te*4
    int tgB = tid >> 4;       // gB = tgB*4

    unsigned long long accV[4][2];
#pragma unroll
    for (int i = 0; i < 4; ++i) { accV[i][0] = 0ull; accV[i][1] = 0ull; }

    for (int st = 0; st < 4; ++st) {
        int s0 = ns * 128 + st * 32;
        __syncthreads();
        // stage K (transposed) and values (straight)
#pragma unroll
        for (int v = 0; v < 2; ++v) {
            int idx = v * 256 + tid;
            int si = idx >> 4, e4 = (idx & 15) * 4;
            long gbase = ((long)(b * 1024 + s0 + si) * 8 + h) * 64 + e4;
            float4 kv = *(const float4*)(K + gbase);
            sKt[e4 + 0][si] = kv.x;
            sKt[e4 + 1][si] = kv.y;
            sKt[e4 + 2][si] = kv.z;
            sKt[e4 + 3][si] = kv.w;
            *(float4*)&sV[si][e4] = *(const float4*)(V + gbase);
        }
        __syncthreads();

        // phase A: logits[2 s][4 g]
        unsigned long long accL[2][2];
        accL[0][0] = accL[0][1] = accL[1][0] = accL[1][1] = 0ull;
#pragma unroll 16
        for (int e = 0; e < 64; ++e) {
            float2 kk = *(const float2*)&sKt[e][ts * 2];
            ulonglong2 tt = *(const ulonglong2*)&sT[e][tgA * 4];
            unsigned long long k0 = pack2(kk.x, kk.x);
            unsigned long long k1 = pack2(kk.y, kk.y);
            fma2(accL[0][0], k0, tt.x); fma2(accL[0][1], k0, tt.y);
            fma2(accL[1][0], k1, tt.x); fma2(accL[1][1], k1, tt.y);
        }
        // softmax over 64 g (4 local + 16 lanes), scale = 1/sqrt(64)
#pragma unroll
        for (int r = 0; r < 2; ++r) {
            float2 a = unpack2(accL[r][0]);
            float2 c = unpack2(accL[r][1]);
            float l0 = 0.125f * a.x, l1 = 0.125f * a.y, l2 = 0.125f * c.x, l3 = 0.125f * c.y;
            float mx = fmaxf(fmaxf(l0, l1), fmaxf(l2, l3));
#pragma unroll
            for (int off = 8; off > 0; off >>= 1)
                mx = fmaxf(mx, __shfl_xor_sync(0xffffffffu, mx, off));
            float p0 = __expf(l0 - mx), p1 = __expf(l1 - mx);
            float p2 = __expf(l2 - mx), p3 = __expf(l3 - mx);
            float sum = p0 + p1 + p2 + p3;
#pragma unroll
            for (int off = 8; off > 0; off >>= 1)
                sum += __shfl_xor_sync(0xffffffffu, sum, off);
            float inv = 1.0f / sum;
            *(float4*)&sP[ts * 2 + r][tgA * 4] = make_float4(p0 * inv, p1 * inv, p2 * inv, p3 * inv);
        }
        __syncthreads();

        // phase B: accV[e][g] += v[s][e] * P[s][g]
#pragma unroll 8
        for (int s = 0; s < 32; ++s) {
            float4 vv = *(const float4*)&sV[s][te * 4];
            ulonglong2 pp = *(const ulonglong2*)&sP[s][tgB * 4];
            unsigned long long v2;
            v2 = pack2(vv.x, vv.x); fma2(accV[0][0], v2, pp.x); fma2(accV[0][1], v2, pp.y);
            v2 = pack2(vv.y, vv.y); fma2(accV[1][0], v2, pp.x); fma2(accV[1][1], v2, pp.y);
            v2 = pack2(vv.z, vv.z); fma2(accV[2][0], v2, pp.x); fma2(accV[2][1], v2, pp.y);
            v2 = pack2(vv.w, vv.w); fma2(accV[3][0], v2, pp.x); fma2(accV[3][1], v2, pp.y);
        }
    }

    // epilogue: out[b, e, h, g] layout [16,64,8,64]
#pragma unroll
    for (int i = 0; i < 4; ++i) {
        int e = te * 4 + i;
        long obase = ((long)(b * 64 + e) * 8 + h) * 64 + tgB * 4;
#pragma unroll
        for (int jp = 0; jp < 2; ++jp) {
            float2 v = unpack2(accV[i][jp]);
            atomicAdd(&out[obase + jp * 2 + 0], v.x);
            atomicAdd(&out[obase + jp * 2 + 1], v.y);
        }
    }
}

extern "C" void kernel_launch(void* const* d_in, const int* in_sizes, int n_in,
                              void* d_out, int out_size) {
    const float* q  = (const float*)d_in[0];
    const float* k  = (const float*)d_in[1];
    const float* v  = (const float*)d_in[2];
    const float* x  = (const float*)d_in[3];
    const float* mw = (const float*)d_in[4];
    const float* mb = (const float*)d_in[5];
    const float* sW = (const float*)d_in[6];
    (void)in_sizes; (void)n_in; (void)out_size;
    float* out = (float*)d_out;

    k0_zero<<<2048, 256>>>(out);                 // zero out + g_T (524288 each)
    k1_mlp<<<1024, 256>>>(x, mw, mb);            // 16 rows per CTA
    k2_T<<<dim3(8, NH, NB), 256>>>(q, sW);       // T = Q^T * sel
    k3_attn<<<dim3(8, NH, NB), 256>>>(k, v, out);// logits/softmax/V
}

// round 4
// speedup vs baseline: 1.3809x; 1.3264x over previous
#include <cuda_runtime.h>
typedef unsigned long long u64;
#define NB 16
#define NH 8

__device__ float g_m[NB * NH * 1024];   // tanh-MLP, [b][h][n]
__device__ float g_A[NB * NH * 128];    // per (b,h): A+[64], A-[64]

__device__ __forceinline__ u64 pack2(float a, float b) {
    u64 r; asm("mov.b64 %0,{%1,%2};" : "=l"(r) : "f"(a), "f"(b)); return r;
}
__device__ __forceinline__ void fma2(u64& d, u64 a, u64 b) {
    asm("fma.rn.f32x2 %0,%1,%2,%0;" : "+l"(d) : "l"(a), "l"(b));
}
__device__ __forceinline__ float2 unpack2(u64 v) {
    float2 r; asm("mov.b64 {%0,%1},%2;" : "=f"(r.x), "=f"(r.y) : "l"(v)); return r;
}
__device__ __forceinline__ unsigned su32(const void* p) {
    unsigned r;
    asm("{.reg .u64 t; cvta.to.shared.u64 t,%1; cvt.u32.u64 %0,t;}" : "=r"(r) : "l"(p));
    return r;
}
#define CP16(d, s) asm volatile("cp.async.cg.shared.global [%0],[%1],16;" :: "r"(d), "l"(s))
#define CPC()      asm volatile("cp.async.commit_group;")

// ---------- k1: MLP m[b,h,n] = tanh(x@W^T + b), raw-reshape mapping ----------
__global__ void __launch_bounds__(256) k1_mlp(const float* __restrict__ x,
                                              const float* __restrict__ w,
                                              const float* __restrict__ bias) {
    __shared__ __align__(16) float sw[8 * 1024];
    __shared__ float sb[8];
    int tid = threadIdx.x;
    for (int i = tid; i < 2048; i += 256)
        ((float4*)sw)[i] = ((const float4*)w)[i];
    if (tid < 8) sb[tid] = bias[tid];
    __syncthreads();
    int warp = tid >> 5, lane = tid & 31;
#pragma unroll
    for (int rr = 0; rr < 2; ++rr) {
        int row = blockIdx.x * 16 + warp * 2 + rr;
        const float4* xr = (const float4*)(x + (long)row * 1024);
        float acc[8];
#pragma unroll
        for (int h = 0; h < 8; ++h) acc[h] = 0.0f;
#pragma unroll
        for (int j = 0; j < 8; ++j) {
            int k4 = lane * 4 + j * 128;
            float4 xv = xr[k4 >> 2];
#pragma unroll
            for (int h = 0; h < 8; ++h) {
                float4 wv = *(const float4*)&sw[h * 1024 + k4];
                acc[h] += xv.x * wv.x + xv.y * wv.y + xv.z * wv.z + xv.w * wv.w;
            }
        }
#pragma unroll
        for (int h = 0; h < 8; ++h)
#pragma unroll
            for (int off = 16; off > 0; off >>= 1)
                acc[h] += __shfl_xor_sync(0xffffffffu, acc[h], off);
        if (lane < 8) {
            float v = tanhf(acc[lane] + sb[lane]);
            int b = row >> 10, j = row & 1023;
            int h = j >> 7, n = ((j & 127) << 3) + lane;
            g_m[(b * 8 + h) * 1024 + n] = v;
        }
    }
}

// ---------- k2: A+/-[e] = sum_n max/min(m,0) * Q[b,n,h,e] ----------
__global__ void __launch_bounds__(256) k2_A(const float* __restrict__ Q) {
    int h = blockIdx.x, b = blockIdx.y, tid = threadIdx.x;
    int e = tid & 63, stripe = tid >> 6;
    const float* mp = g_m + (b * 8 + h) * 1024 + stripe * 256;
    const float* qp = Q + ((long)(b * 1024 + stripe * 256) * 8 + h) * 64 + e;
    float ap = 0.f, an = 0.f;
#pragma unroll 8
    for (int n = 0; n < 256; ++n) {
        float m = mp[n];
        float qv = qp[(long)n * 512];
        ap += fmaxf(m, 0.f) * qv;
        an += fminf(m, 0.f) * qv;
    }
    __shared__ float sp[4][64], sn[4][64];
    sp[stripe][e] = ap; sn[stripe][e] = an;
    __syncthreads();
    if (tid < 64)
        g_A[(b * 8 + h) * 128 + tid] = sp[0][tid] + sp[1][tid] + sp[2][tid] + sp[3][tid];
    else if (tid < 128) {
        int e2 = tid - 64;
        g_A[(b * 8 + h) * 128 + 64 + e2] = sn[0][e2] + sn[1][e2] + sn[2][e2] + sn[3][e2];
    }
}

// ---------- k3: u,t = K·A+-, rank-2 softmax, out[e,g] = sum_s V[s,e] P[s,g] ----------
// SM floats: sK[2][32][68] @0, sV[2][32][68] @4352, sP[32][68] @8704 (total 10880)
__global__ void __launch_bounds__(256, 1) k3_attn(const float* __restrict__ K,
                                                  const float* __restrict__ V,
                                                  const float* __restrict__ sW,
                                                  float* __restrict__ out) {
    __shared__ __align__(16) float SM[10880];
    float* sP = SM + 8704;
    const int h = blockIdx.x, b = blockIdx.y, tid = threadIdx.x;
    const unsigned smb = su32(SM);
    const int part = tid & 7, sl = tid >> 3;
    const int quarter = tid >> 6, eg = (tid >> 3) & 7, gg = tid & 7;

    float rAp[8], rAn[8], ra[8], rc[8];
    const float* Ab = g_A + (b * 8 + h) * 128;
#pragma unroll
    for (int i = 0; i < 8; ++i) { rAp[i] = Ab[part * 8 + i]; rAn[i] = Ab[64 + part * 8 + i]; }
#pragma unroll
    for (int j = 0; j < 8; ++j) {
        float w = sW[h * 64 + part * 8 + j];
        ra[j] = 0.125f * fmaxf(w, 0.f);
        rc[j] = 0.125f * fminf(w, 0.f);
    }

    const float* Kb = K + ((long)b * 8192 + h) * 64;
    const float* Vb = V + ((long)b * 8192 + h) * 64;

    // prologue: stage tile 0 into buffer 0
#pragma unroll
    for (int i = 0; i < 2; ++i) {
        int idx = i * 256 + tid;
        int row = idx >> 4, col = (idx & 15) << 2;
        long go = (long)row * 512 + col;
        unsigned so = ((unsigned)(row * 68 + col)) << 2;
        CP16(smb + so, Kb + go);
        CP16(smb + 4352 * 4 + so, Vb + go);
    }
    CPC();

    u64 acc[32];
#pragma unroll
    for (int i = 0; i < 32; ++i) acc[i] = 0ull;

    for (int t = 0; t < 32; ++t) {
        int buf = t & 1;
        if (t + 1 < 32) {
            int s0 = (t + 1) * 32, nb = buf ^ 1;
#pragma unroll
            for (int i = 0; i < 2; ++i) {
                int idx = i * 256 + tid;
                int row = idx >> 4, col = (idx & 15) << 2;
                long go = (long)(s0 + row) * 512 + col;
                unsigned so = ((unsigned)(nb * 2176 + row * 68 + col)) << 2;
                CP16(smb + so, Kb + go);
                CP16(smb + 4352 * 4 + so, Vb + go);
            }
            CPC();
            asm volatile("cp.async.wait_group 1;");
        } else {
            asm volatile("cp.async.wait_group 0;");
        }
        __syncthreads();

        // u,t for s = sl (8 lanes each cover 8 e)
        const float* kr = SM + buf * 2176 + sl * 68 + part * 8;
        float u = 0.f, tt = 0.f;
#pragma unroll
        for (int i = 0; i < 8; ++i) { float kv = kr[i]; u += kv * rAp[i]; tt += kv * rAn[i]; }
#pragma unroll
        for (int off = 1; off < 8; off <<= 1) {
            u  += __shfl_xor_sync(0xffffffffu, u,  off);
            tt += __shfl_xor_sync(0xffffffffu, tt, off);
        }
        // softmax slice: 8 g per thread
        float l[8], mx = -1e30f;
#pragma unroll
        for (int j = 0; j < 8; ++j) { l[j] = u * ra[j] + tt * rc[j]; mx = fmaxf(mx, l[j]); }
#pragma unroll
        for (int off = 1; off < 8; off <<= 1)
            mx = fmaxf(mx, __shfl_xor_sync(0xffffffffu, mx, off));
        float sum = 0.f;
#pragma unroll
        for (int j = 0; j < 8; ++j) { l[j] = __expf(l[j] - mx); sum += l[j]; }
#pragma unroll
        for (int off = 1; off < 8; off <<= 1)
            sum += __shfl_xor_sync(0xffffffffu, sum, off);
        float inv = __fdividef(1.f, sum);
        *(float4*)&sP[sl * 68 + part * 8]     = make_float4(l[0] * inv, l[1] * inv, l[2] * inv, l[3] * inv);
        *(float4*)&sP[sl * 68 + part * 8 + 4] = make_float4(l[4] * inv, l[5] * inv, l[6] * inv, l[7] * inv);
        __syncthreads();

        // phase B: each quarter covers full 64x64 over its 8 s
        const float* vb = SM + 4352 + buf * 2176;
#pragma unroll
        for (int s8 = 0; s8 < 8; ++s8) {
            int sq = quarter * 8 + s8;
            float4 v0 = *(const float4*)&vb[sq * 68 + eg * 8];
            float4 v1 = *(const float4*)&vb[sq * 68 + eg * 8 + 4];
            ulonglong2 pA = *(const ulonglong2*)&sP[sq * 68 + gg * 8];
            ulonglong2 pB = *(const ulonglong2*)&sP[sq * 68 + gg * 8 + 4];
            float ve[8] = {v0.x, v0.y, v0.z, v0.w, v1.x, v1.y, v1.z, v1.w};
#pragma unroll
            for (int e = 0; e < 8; ++e) {
                u64 vv = pack2(ve[e], ve[e]);
                fma2(acc[e * 4 + 0], vv, pA.x);
                fma2(acc[e * 4 + 1], vv, pA.y);
                fma2(acc[e * 4 + 2], vv, pB.x);
                fma2(acc[e * 4 + 3], vv, pB.y);
            }
        }
        __syncthreads();
    }

    // reduce the 4 quarter-copies (reuse sK/sV region as u64 buffer)
    u64* sred = (u64*)SM;
    if (tid >= 128) {
        int j = tid - 128;
#pragma unroll
        for (int i = 0; i < 32; ++i) sred[j * 32 + i] = acc[i];
    }
    __syncthreads();
    if (tid < 128) {
#pragma unroll
        for (int i = 0; i < 32; ++i) {
            float2 a = unpack2(acc[i]), c = unpack2(sred[tid * 32 + i]);
            acc[i] = pack2(a.x + c.x, a.y + c.y);
        }
    }
    __syncthreads();
    if (tid >= 64 && tid < 128) {
#pragma unroll
        for (int i = 0; i < 32; ++i) sred[(tid - 64) * 32 + i] = acc[i];
    }
    __syncthreads();
    if (tid < 64) {
#pragma unroll
        for (int i = 0; i < 32; ++i) {
            float2 a = unpack2(acc[i]), c = unpack2(sred[tid * 32 + i]);
            acc[i] = pack2(a.x + c.x, a.y + c.y);
        }
        // out[b, e, h, g]
#pragma unroll
        for (int e = 0; e < 8; ++e) {
            long ob = ((long)(b * 64 + eg * 8 + e) * 8 + h) * 64 + gg * 8;
            float2 p0 = unpack2(acc[e * 4 + 0]), p1 = unpack2(acc[e * 4 + 1]);
            float2 p2 = unpack2(acc[e * 4 + 2]), p3 = unpack2(acc[e * 4 + 3]);
            *(float4*)&out[ob]     = make_float4(p0.x, p0.y, p1.x, p1.y);
            *(float4*)&out[ob + 4] = make_float4(p2.x, p2.y, p3.x, p3.y);
        }
    }
}

extern "C" void kernel_launch(void* const* d_in, const int* in_sizes, int n_in,
                              void* d_out, int out_size) {
    const float* q  = (const float*)d_in[0];
    const float* k  = (const float*)d_in[1];
    const float* v  = (const float*)d_in[2];
    const float* x  = (const float*)d_in[3];
    const float* mw = (const float*)d_in[4];
    const float* mb = (const float*)d_in[5];
    const float* sW = (const float*)d_in[6];
    (void)in_sizes; (void)n_in; (void)out_size;
    float* out = (float*)d_out;

    k1_mlp<<<1024, 256>>>(x, mw, mb);
    k2_A<<<dim3(NH, NB), 256>>>(q);
    k3_attn<<<dim3(NH, NB), 256>>>(k, v, sW, out);
}